// round 16
// baseline (speedup 1.0000x reference)
#include <cuda_runtime.h>
#include <cuda_fp16.h>
#include <stdint.h>

#define NP      8
#define NP1     9
#define IN_D    10
#define THREADS 192          // 6 compute warps, m16 each
#define TILE_M  96

// fp16 fragment-ordered weight image:
//   L0 @ 0 (4KB) | L1 @ 4096 (32KB) | L2 @ 36864 (32KB) | L3 @ 69632 (32KB)
//   W4 @ 102400 (2KB) | W56 @ 104448 (512B)
__device__ __align__(16) unsigned char g_W[105216];

#define OFF_W4 102400
#define W_BYTES 105216u

// ---------------- helpers ----------------
__device__ __forceinline__ uint32_t smem_u32(const void* p){
    uint32_t a;
    asm("{ .reg .u64 t; cvta.to.shared.u64 t, %1; cvt.u32.u64 %0, t; }" : "=r"(a) : "l"(p));
    return a;
}
__device__ __forceinline__ uint32_t packf16(float x0, float x1){ // x0 -> low half
    uint32_t r; asm("cvt.rn.f16x2.f32 %0, %1, %2;" : "=r"(r) : "f"(x1), "f"(x0)); return r;
}

#define MBAR_INIT(a,c)   asm volatile("mbarrier.init.shared.b64 [%0], %1;" :: "r"(a), "r"(c) : "memory")
#define MBAR_EXPECT(a,b) asm volatile("mbarrier.arrive.expect_tx.shared.b64 _, [%0], %1;" :: "r"(a), "r"(b) : "memory")
#define FENCE_PROXY()    asm volatile("fence.proxy.async.shared::cta;" ::: "memory")

__device__ __forceinline__ void mbar_wait(uint32_t mbar, uint32_t parity){
    asm volatile(
        "{\n\t.reg .pred P;\n\t"
        "WL_%=:\n\t"
        "mbarrier.try_wait.parity.acquire.cta.shared::cta.b64 P, [%0], %1, 0x989680;\n\t"
        "@P bra.uni WD_%=;\n\t"
        "bra.uni WL_%=;\n\t"
        "WD_%=:\n\t}"
        :: "r"(mbar), "r"(parity) : "memory");
}
__device__ __forceinline__ void bulk_copy(uint32_t dst, const void* src, uint32_t bytes, uint32_t mbar){
    asm volatile(
        "cp.async.bulk.shared::cta.global.mbarrier::complete_tx::bytes [%0], [%1], %2, [%3];"
        :: "r"(dst), "l"(src), "r"(bytes), "r"(mbar) : "memory");
}

#define CP_ASYNC8(dst, src) \
    asm volatile("cp.async.ca.shared.global [%0], [%1], 8;" :: "r"(dst), "l"(src) : "memory")
#define CP_ASYNC4(dst, src) \
    asm volatile("cp.async.ca.shared.global [%0], [%1], 4;" :: "r"(dst), "l"(src) : "memory")
#define CP_COMMIT() asm volatile("cp.async.commit_group;" ::: "memory")
#define CP_WAIT0()  asm volatile("cp.async.wait_group 0;" ::: "memory")

#define LDS128(r0,r1,r2,r3,addr) \
    asm volatile("ld.shared.v4.b32 {%0,%1,%2,%3}, [%4];" : "=r"(r0),"=r"(r1),"=r"(r2),"=r"(r3) : "r"(addr))
#define LDS64(r0,r1,addr) \
    asm volatile("ld.shared.v2.b32 {%0,%1}, [%2];" : "=r"(r0),"=r"(r1) : "r"(addr))
#define LDS32U(r,addr) \
    asm volatile("ld.shared.b32 %0, [%1];" : "=r"(r) : "r"(addr))

#define HADD2(d, b) asm("add.rn.f16x2 %0, %0, %1;" : "+r"(d) : "r"(b))
#define HMAX2Z(d)   asm("max.f16x2 %0, %0, %1;"    : "+r"(d) : "r"(0u))

#define MMA_F16(C, a0,a1,a2,a3, b0,b1) \
    asm volatile("mma.sync.aligned.m16n8k16.row.col.f32.f16.f16.f32 " \
        "{%0,%1,%2,%3}, {%4,%5,%6,%7}, {%8,%9}, {%0,%1,%2,%3};" \
        : "+f"((C)[0]), "+f"((C)[1]), "+f"((C)[2]), "+f"((C)[3]) \
        : "r"(a0), "r"(a1), "r"(a2), "r"(a3), "r"(b0), "r"(b1))

// ---------------- weight prep (unchanged layout) ----------------
__global__ void prep_kernel(const float* __restrict__ W0, const float* __restrict__ W1,
                            const float* __restrict__ W2, const float* __restrict__ W3,
                            const float* __restrict__ W4, const float* __restrict__ W5,
                            const float* __restrict__ W6)
{
    const int layer = blockIdx.y;
    const int idx   = blockIdx.x * 256 + threadIdx.x;
    const int lane  = idx & 31;
    const int g     = lane >> 2;
    const int t     = lane & 3;

    if (layer <= 3) {
        const int rest = idx >> 5;
        const int ntp  = rest & 7;
        const int ks   = rest >> 3;
        if (ks > 7) return;
        if (layer == 0 && ks > 0) return;

        const float* W = (layer == 0) ? W0 : (layer == 1) ? W1 : (layer == 2) ? W2 : W3;
        const int KMAX = (layer == 0) ? IN_D : 128;

        uint32_t hi[4];
        #pragma unroll
        for (int h = 0; h < 2; h++) {
            const int n  = (2*ntp + h) * 8 + g;
            const int kb = ks * 16;
            const int kr[4] = { kb + 2*t, kb + 2*t + 1, kb + 2*t + 8, kb + 2*t + 9 };
            float v[4];
            #pragma unroll
            for (int i = 0; i < 4; i++)
                v[i] = (kr[i] < KMAX) ? __ldg(W + kr[i] * 128 + n) : 0.f;
            hi[2*h]   = packf16(v[0], v[1]);
            hi[2*h+1] = packf16(v[2], v[3]);
        }
        const size_t lbase = (layer == 0) ? 0 : (4096 + (size_t)(layer-1) * 32768);
        const size_t off   = (size_t)((ks*8 + ntp) * 32 + lane) * 16;
        *(uint4*)(&g_W[lbase + off]) = make_uint4(hi[0],hi[1],hi[2],hi[3]);
        return;
    }

    if (layer == 4) {                        // W4 [128][8]
        if (idx >= 256) return;
        const int ks = idx >> 5;
        const int kb = ks * 16;
        const int kr[4] = { kb + 2*t, kb + 2*t + 1, kb + 2*t + 8, kb + 2*t + 9 };
        float v[4];
        #pragma unroll
        for (int i = 0; i < 4; i++) v[i] = __ldg(W4 + kr[i] * NP + g);
        uint2* dst = (uint2*)(&g_W[OFF_W4 + (size_t)(ks*32 + lane) * 8]);
        *dst = make_uint2(packf16(v[0], v[1]), packf16(v[2], v[3]));
        return;
    }
    if (layer == 5) {                        // W56 = W5 @ W6  [8][10], k pad16, n pad16
        if (idx >= 32) return;
        const int kr[4] = { 2*t, 2*t + 1, 2*t + 8, 2*t + 9 };
        uint32_t w[4];
        #pragma unroll
        for (int h = 0; h < 2; h++) {
            const int n = h * 8 + g;
            float v[4];
            #pragma unroll
            for (int i = 0; i < 4; i++) {
                float s = 0.f;
                if (kr[i] < 8 && n < IN_D) {
                    #pragma unroll
                    for (int m = 0; m < 8; m++)
                        s += __ldg(W5 + kr[i] * NP + m) * __ldg(W6 + m * IN_D + n);
                }
                v[i] = s;
            }
            w[2*h]   = packf16(v[0], v[1]);
            w[2*h+1] = packf16(v[2], v[3]);
        }
        *(uint4*)(&g_W[102400 + 2048 + (size_t)lane * 16]) = make_uint4(w[0],w[1],w[2],w[3]);
        return;
    }
}

// pack one nt-pair (j) of finished accs into next-layer A chunk j; zero accs (m16)
template <bool RELU>
__device__ __forceinline__ void pack_nt(float acc[16][4], uint32_t aH[8][4],
                                        uint32_t biasLA, int c, int j)
{
    #pragma unroll
    for (int h = 0; h < 2; h++) {
        const int nt = 2*j + h;
        uint32_t bh;
        LDS32U(bh, biasLA + (uint32_t)((nt*4 + c)*4));
        uint32_t p0 = packf16(acc[nt][0], acc[nt][1]);
        uint32_t p1 = packf16(acc[nt][2], acc[nt][3]);
        HADD2(p0, bh); HADD2(p1, bh);
        if (RELU) { HMAX2Z(p0); HMAX2Z(p1); }
        aH[j][2*h]   = p0;
        aH[j][2*h+1] = p1;
        acc[nt][0]=0.f; acc[nt][1]=0.f; acc[nt][2]=0.f; acc[nt][3]=0.f;
    }
}

// full layer + folded boundary (m16)
template <int NKS, bool RELU>
__device__ __forceinline__ void run_layer_fold(float acc[16][4], uint32_t aH[8][4],
                                               uint32_t wbase, uint32_t biasLA,
                                               int lane, int c)
{
    const uint32_t lof = (uint32_t)lane * 16u;
    #pragma unroll
    for (int ks = 0; ks < NKS - 1; ks++) {
        uint32_t w[8][4];
        #pragma unroll
        for (int ntp = 0; ntp < 8; ntp++)
            LDS128(w[ntp][0],w[ntp][1],w[ntp][2],w[ntp][3],
                   wbase + (uint32_t)((ks*8 + ntp)*32)*16u + lof);
        #pragma unroll
        for (int ntp = 0; ntp < 8; ntp++) {
            MMA_F16(acc[2*ntp],   aH[ks][0],aH[ks][1],aH[ks][2],aH[ks][3], w[ntp][0],w[ntp][1]);
            MMA_F16(acc[2*ntp+1], aH[ks][0],aH[ks][1],aH[ks][2],aH[ks][3], w[ntp][2],w[ntp][3]);
        }
    }
    {   // last ks: MMAs with pack(ntp-1) folded in
        const int ks = NKS - 1;
        uint32_t w[8][4];
        #pragma unroll
        for (int ntp = 0; ntp < 8; ntp++)
            LDS128(w[ntp][0],w[ntp][1],w[ntp][2],w[ntp][3],
                   wbase + (uint32_t)((ks*8 + ntp)*32)*16u + lof);
        #pragma unroll
        for (int ntp = 0; ntp < 8; ntp++) {
            MMA_F16(acc[2*ntp],   aH[ks][0],aH[ks][1],aH[ks][2],aH[ks][3], w[ntp][0],w[ntp][1]);
            MMA_F16(acc[2*ntp+1], aH[ks][0],aH[ks][1],aH[ks][2],aH[ks][3], w[ntp][2],w[ntp][3]);
            if (ntp > 0) pack_nt<RELU>(acc, aH, biasLA, c, ntp - 1);
        }
        pack_nt<RELU>(acc, aH, biasLA, c, 7);
    }
}

// L0 (single k-slice) with folded boundary (m16)
__device__ __forceinline__ void run_layer0_fold(float acc[16][4], uint32_t aH[8][4],
                                                uint32_t wbase, uint32_t biasLA,
                                                int lane, int c)
{
    const uint32_t lof = (uint32_t)lane * 16u;
    uint32_t a0[4];
    #pragma unroll
    for (int i = 0; i < 4; i++) a0[i] = aH[0][i];

    #pragma unroll
    for (int ntp = 0; ntp < 8; ntp++) {
        uint32_t w0,w1,w2,w3;
        LDS128(w0,w1,w2,w3, wbase + (uint32_t)(ntp*32)*16u + lof);
        MMA_F16(acc[2*ntp],   a0[0],a0[1],a0[2],a0[3], w0,w1);
        MMA_F16(acc[2*ntp+1], a0[0],a0[1],a0[2],a0[3], w2,w3);
        if (ntp > 0) pack_nt<true>(acc, aH, biasLA, c, ntp - 1);
    }
    pack_nt<true>(acc, aH, biasLA, c, 7);
}

__device__ __forceinline__ float frag_val(const float* srow, int col){
    if (col >= IN_D) return 0.f;
    const int off = (col == 0) ? 8 : (col == 9) ? 9 : (col - 1);
    return srow[off];
}

// ---------------- main kernel: 12 warps/SM (2 CTAs x 6 warps, m16 each) ----------------
__global__ void __launch_bounds__(THREADS, 2)
ElementGNN_m16_kernel(const float* __restrict__ data,
                      const int*   __restrict__ elements,
                      const float* __restrict__ b0, const float* __restrict__ b1,
                      const float* __restrict__ b2, const float* __restrict__ b3,
                      const float* __restrict__ b4, const float* __restrict__ b5,
                      const float* __restrict__ b6, const float* __restrict__ W6,
                      float* __restrict__ out, int k)
{
    extern __shared__ char smraw[];
    const uint32_t raw = smem_u32(smraw);
    const uint32_t s0  = (raw + 1023u) & ~1023u;
    char* base = smraw + (s0 - raw);

    const uint32_t wL0   = s0;                     // 4KB
    const uint32_t wL1   = s0 + 4096u;
    const uint32_t wL2   = s0 + 36864u;
    const uint32_t wL3   = s0 + 69632u;
    const uint32_t sTail = s0 + 102400u;           // W4 2KB | W56 512B
    float* s_in  = (float*)(base + 104960);        // [96][10] staging (3840B)
    const uint32_t sInA = s0 + 104960u;
    int* sE0 = (int*)(base + 108800);              // 384B
    int* sE1 = (int*)(base + 109184);              // 384B
    const uint32_t biasH = s0 + 109568u;           // [4][16][4] u32 (1024B)
    uint32_t* biasHp = (uint32_t*)(base + 109568);
    float* sB456 = (float*)(base + 110592);        // b4p[4] @u32, b56f[10] @ +32
    const uint32_t sB456A = s0 + 110592u;
    const uint32_t fullW = s0 + 110720u;

    const int tid  = threadIdx.x;
    const int warp = tid >> 5;
    const int lane = tid & 31;
    const int gr = lane >> 2, c = lane & 3;
    const int rl   = lane & 15;                    // gather row-in-warp
    const int rowG = warp * 16 + rl;
    const int STRIDE = gridDim.x * TILE_M;

    if (tid == 0) { MBAR_INIT(fullW, 1); FENCE_PROXY(); }
    __syncthreads();
    if (tid == 0) { MBAR_EXPECT(fullW, W_BYTES); bulk_copy(wL0, &g_W[0], W_BYTES, fullW); }

    // bias staging (once)
    for (int i = tid; i < 256; i += THREADS) {
        const int layer = i >> 6, r = i & 63, nt = r >> 2, cc = r & 3;
        const float* bsrc = (layer==0)?b0:(layer==1)?b1:(layer==2)?b2:b3;
        biasHp[i] = packf16(__ldg(bsrc + nt*8 + 2*cc), __ldg(bsrc + nt*8 + 2*cc + 1));
    }
    if (tid < 4)
        ((uint32_t*)sB456)[tid] = packf16(__ldg(b4 + 2*tid), __ldg(b4 + 2*tid + 1));
    if (tid < 10) {                                  // b56 = b6 + b5 @ W6
        float s = __ldg(b6 + tid);
        #pragma unroll
        for (int i = 0; i < 8; i++) s += __ldg(b5 + i) * __ldg(W6 + i * IN_D + tid);
        sB456[8 + tid] = s;
    }
    const float* b56f = sB456 + 8;

    // ---- prologue gather for tile 0 (warp-private: lanes 0-15 data, 16-31 halo) ----
    const int tb0 = blockIdx.x * TILE_M;
    int evN;
    {
        const int pos0 = tb0 + rowG;
        const int ev0 = __ldg(elements + ((pos0 < k) ? pos0 : (k - 1)));
        const int e0 = ev0 / NP1;
        const uint32_t dst = sInA + (uint32_t)rowG * 40u;
        if (lane < 16) {
            sE0[rowG] = e0;
            const float* so = data + (size_t)e0 * NP;
            CP_ASYNC8(dst,      so);
            CP_ASYNC8(dst + 8,  so + 2);
            CP_ASYNC8(dst + 16, so + 4);
            CP_ASYNC8(dst + 24, so + 6);
        } else {
            const int le = (e0 == 0) ? (k - 1) : (e0 - 1);
            const int ri = (e0 == k - 1) ? 0 : (e0 + 1);
            CP_ASYNC4(dst + 32, data + (size_t)le * NP + (NP - 1));
            CP_ASYNC4(dst + 36, data + (size_t)ri * NP);
        }
        CP_COMMIT();
        const int pos1 = tb0 + STRIDE + rowG;
        evN = __ldg(elements + ((pos1 < k) ? pos1 : (k - 1)));
    }
    __syncthreads();
    mbar_wait(fullW, 0);

    float acc[16][4];
    #pragma unroll
    for (int i = 0; i < 16; i++) {
        acc[i][0]=0.f; acc[i][1]=0.f; acc[i][2]=0.f; acc[i][3]=0.f;
    }

    int p = 0;
    for (int tb = tb0; tb < k; tb += STRIDE) {
        int* sE_cur = p ? sE1 : sE0;
        int* sE_nxt = p ? sE0 : sE1;

        CP_WAIT0();
        __syncwarp();

        // layer-0 A frags from staging (m16: rows warp*16+gr, +8)
        uint32_t aH[8][4];
        {
            const float* srow0 = s_in + (size_t)(warp*16 + gr) * 10;
            const float* srow1 = srow0 + 80;
            const int cols[4] = { 2*c, 2*c+1, 2*c+8, 2*c+9 };
            float f0[4], f1[4];
            #pragma unroll
            for (int i = 0; i < 4; i++) {
                f0[i] = frag_val(srow0, cols[i]);
                f1[i] = frag_val(srow1, cols[i]);
            }
            aH[0][0] = packf16(f0[0], f0[1]);
            aH[0][1] = packf16(f1[0], f1[1]);
            aH[0][2] = packf16(f0[2], f0[3]);
            aH[0][3] = packf16(f1[2], f1[3]);
        }

        // issue next-tile gather (warp-private rows)
        const int nb = tb + STRIDE;
        if (nb < k) {
            const int eN = evN / NP1;
            const uint32_t dst = sInA + (uint32_t)rowG * 40u;
            if (lane < 16) {
                sE_nxt[rowG] = eN;
                const float* so = data + (size_t)eN * NP;
                CP_ASYNC8(dst,      so);
                CP_ASYNC8(dst + 8,  so + 2);
                CP_ASYNC8(dst + 16, so + 4);
                CP_ASYNC8(dst + 24, so + 6);
            } else {
                const int le = (eN == 0) ? (k - 1) : (eN - 1);
                const int ri = (eN == k - 1) ? 0 : (eN + 1);
                CP_ASYNC4(dst + 32, data + (size_t)le * NP + (NP - 1));
                CP_ASYNC4(dst + 36, data + (size_t)ri * NP);
            }
            const int pos2 = nb + STRIDE + rowG;
            evN = __ldg(elements + ((pos2 < k) ? pos2 : (k - 1)));
        }
        CP_COMMIT();

        // trunk: all boundaries folded
        run_layer0_fold(acc, aH, wL0, biasH + 0*256u, lane, c);
        run_layer_fold<8, false>(acc, aH, wL1, biasH + 1*256u, lane, c);
        run_layer_fold<8, true >(acc, aH, wL2, biasH + 2*256u, lane, c);
        run_layer_fold<8, false>(acc, aH, wL3, biasH + 3*256u, lane, c);
        // aH = fp16(L3 output), acc zeroed

        // ---- hoisted residual loads ----
        float rvA[2], rvB[2];
        #pragma unroll
        for (int rh = 0; rh < 2; rh++) {
            const int rowT = warp*16 + rh*8 + gr;
            const int pos  = tb + rowT;
            rvA[rh] = 0.f; rvB[rh] = 0.f;
            if (pos < k) {
                const int eR = sE_cur[rowT];
                const float* dp = data + (size_t)eR * NP;
                if (c == 0) {
                    rvA[rh] = __ldg(dp + 0);
                    rvB[rh] = __ldg(dp + 7);
                } else {
                    rvA[rh] = __ldg(dp + 2*c - 1);
                    rvB[rh] = __ldg(dp + 2*c);
                }
            }
        }

        // ---- MMA tail: W4 -> relu -> W56 ----
        float a4[4];
        a4[0]=0.f; a4[1]=0.f; a4[2]=0.f; a4[3]=0.f;
        {
            const uint32_t tb2 = sTail + (uint32_t)lane * 8u;
            #pragma unroll
            for (int ks = 0; ks < 8; ks++) {
                uint32_t w0, w1;
                LDS64(w0, w1, tb2 + (uint32_t)ks * 256u);
                MMA_F16(a4, aH[ks][0],aH[ks][1],aH[ks][2],aH[ks][3], w0, w1);
            }
        }
        uint32_t hA0, hA1;
        {
            uint32_t b4h; LDS32U(b4h, sB456A + (uint32_t)c * 4u);
            uint32_t q0 = packf16(a4[0], a4[1]);
            uint32_t q1 = packf16(a4[2], a4[3]);
            HADD2(q0, b4h); HADD2(q1, b4h);
            HMAX2Z(q0); HMAX2Z(q1);
            hA0 = q0; hA1 = q1;
        }
        float a6[2][4];
        #pragma unroll
        for (int nt = 0; nt < 2; nt++) {
            a6[nt][0]=0.f; a6[nt][1]=0.f; a6[nt][2]=0.f; a6[nt][3]=0.f;
        }
        {
            uint32_t w0, w1, w2, w3;
            LDS128(w0, w1, w2, w3, sTail + 2048u + (uint32_t)lane * 16u);
            MMA_F16(a6[0], hA0, hA1, 0u, 0u, w0, w1);
            MMA_F16(a6[1], hA0, hA1, 0u, 0u, w2, w3);
        }

        // residual + store
        {
            const float b6c0 = b56f[2*c], b6c1 = b56f[2*c + 1];
            const float b6c8 = b56f[8];
            #pragma unroll
            for (int rh = 0; rh < 2; rh++) {
                const int rowT = warp*16 + rh*8 + gr;
                const int pos  = tb + rowT;
                if (pos < k) {
                    const float f0 = a6[0][rh*2 + 0];
                    const float f1 = a6[0][rh*2 + 1];
                    const float f8 = a6[1][rh*2 + 0];
                    float* op = out + (size_t)pos * NP;
                    if (c == 0) {
                        op[0] = f1 + b6c1 + rvA[rh];
                        op[7] = f8 + b6c8 + rvB[rh];
                    } else {
                        op[2*c - 1] = f0 + b6c0 + rvA[rh];
                        op[2*c]     = f1 + b6c1 + rvB[rh];
                    }
                }
            }
        }
        p ^= 1;
    }
}

// ---------------- launch ----------------
extern "C" void kernel_launch(void* const* d_in, const int* in_sizes, int n_in,
                              void* d_out, int out_size)
{
    const float* data     = (const float*)d_in[0];
    const int*   elements = (const int*)  d_in[1];
    const float* W0 = (const float*)d_in[2];  const float* b0 = (const float*)d_in[3];
    const float* W1 = (const float*)d_in[4];  const float* b1 = (const float*)d_in[5];
    const float* W2 = (const float*)d_in[6];  const float* b2 = (const float*)d_in[7];
    const float* W3 = (const float*)d_in[8];  const float* b3 = (const float*)d_in[9];
    const float* W4 = (const float*)d_in[10]; const float* b4 = (const float*)d_in[11];
    const float* W5 = (const float*)d_in[12]; const float* b5 = (const float*)d_in[13];
    const float* W6 = (const float*)d_in[14]; const float* b6 = (const float*)d_in[15];
    float* out = (float*)d_out;

    const int k = in_sizes[1];

    prep_kernel<<<dim3(8, 6), 256>>>(W0, W1, W2, W3, W4, W5, W6);

    int tiles = (k + TILE_M - 1) / TILE_M;
    int grid  = (tiles < 296) ? tiles : 296;
    const size_t smem = 110728u + 1024u;
    cudaFuncSetAttribute(ElementGNN_m16_kernel,
                         cudaFuncAttributeMaxDynamicSharedMemorySize, (int)smem);
    ElementGNN_m16_kernel<<<grid, THREADS, smem>>>(
        data, elements, b0, b1, b2, b3, b4, b5, b6, W6, out, k);
}

// round 17
// speedup vs baseline: 1.6943x; 1.6943x over previous
#include <cuda_runtime.h>
#include <cuda_fp16.h>
#include <stdint.h>

#define NP      8
#define NP1     9
#define IN_D    10
#define THREADS 128          // 4 compute warps, m32 each
#define TILE_M  128

// fp16 fragment-ordered weight image (fused net):
//   W0 @ 0 (4KB) | W12 @ 4096 (32KB) | W34 @ 36864 (2KB) | W56 @ 38912 (512B)
__device__ __align__(16) unsigned char g_W[39424];
__device__ float g_W12f[16384];
__device__ float g_W34f[1024];

#define W_BYTES 39424u

// ---------------- helpers ----------------
__device__ __forceinline__ uint32_t smem_u32(const void* p){
    uint32_t a;
    asm("{ .reg .u64 t; cvta.to.shared.u64 t, %1; cvt.u32.u64 %0, t; }" : "=r"(a) : "l"(p));
    return a;
}
__device__ __forceinline__ uint32_t packf16(float x0, float x1){ // x0 -> low half
    uint32_t r; asm("cvt.rn.f16x2.f32 %0, %1, %2;" : "=r"(r) : "f"(x1), "f"(x0)); return r;
}

#define MBAR_INIT(a,c)   asm volatile("mbarrier.init.shared.b64 [%0], %1;" :: "r"(a), "r"(c) : "memory")
#define MBAR_EXPECT(a,b) asm volatile("mbarrier.arrive.expect_tx.shared.b64 _, [%0], %1;" :: "r"(a), "r"(b) : "memory")
#define FENCE_PROXY()    asm volatile("fence.proxy.async.shared::cta;" ::: "memory")

__device__ __forceinline__ void mbar_wait(uint32_t mbar, uint32_t parity){
    asm volatile(
        "{\n\t.reg .pred P;\n\t"
        "WL_%=:\n\t"
        "mbarrier.try_wait.parity.acquire.cta.shared::cta.b64 P, [%0], %1, 0x989680;\n\t"
        "@P bra.uni WD_%=;\n\t"
        "bra.uni WL_%=;\n\t"
        "WD_%=:\n\t}"
        :: "r"(mbar), "r"(parity) : "memory");
}
__device__ __forceinline__ void bulk_copy(uint32_t dst, const void* src, uint32_t bytes, uint32_t mbar){
    asm volatile(
        "cp.async.bulk.shared::cta.global.mbarrier::complete_tx::bytes [%0], [%1], %2, [%3];"
        :: "r"(dst), "l"(src), "r"(bytes), "r"(mbar) : "memory");
}

#define CP_ASYNC8(dst, src) \
    asm volatile("cp.async.ca.shared.global [%0], [%1], 8;" :: "r"(dst), "l"(src) : "memory")
#define CP_ASYNC4(dst, src) \
    asm volatile("cp.async.ca.shared.global [%0], [%1], 4;" :: "r"(dst), "l"(src) : "memory")
#define CP_COMMIT() asm volatile("cp.async.commit_group;" ::: "memory")
#define CP_WAIT0()  asm volatile("cp.async.wait_group 0;" ::: "memory")

#define LDS128(r0,r1,r2,r3,addr) \
    asm volatile("ld.shared.v4.b32 {%0,%1,%2,%3}, [%4];" : "=r"(r0),"=r"(r1),"=r"(r2),"=r"(r3) : "r"(addr))
#define LDS64(r0,r1,addr) \
    asm volatile("ld.shared.v2.b32 {%0,%1}, [%2];" : "=r"(r0),"=r"(r1) : "r"(addr))
#define LDS32U(r,addr) \
    asm volatile("ld.shared.b32 %0, [%1];" : "=r"(r) : "r"(addr))

#define HADD2(d, b) asm("add.rn.f16x2 %0, %0, %1;" : "+r"(d) : "r"(b))
#define HMAX2Z(d)   asm("max.f16x2 %0, %0, %1;"    : "+r"(d) : "r"(0u))

#define MMA_F16(C, a0,a1,a2,a3, b0,b1) \
    asm volatile("mma.sync.aligned.m16n8k16.row.col.f32.f16.f16.f32 " \
        "{%0,%1,%2,%3}, {%4,%5,%6,%7}, {%8,%9}, {%0,%1,%2,%3};" \
        : "+f"((C)[0]), "+f"((C)[1]), "+f"((C)[2]), "+f"((C)[3]) \
        : "r"(a0), "r"(a1), "r"(a2), "r"(a3), "r"(b0), "r"(b1))

// ---------------- stage 1: fuse W12 = W1@W2, W34 = W3@W4 in f32 ----------------
__global__ void prep_fuse(const float* __restrict__ W1, const float* __restrict__ W2,
                          const float* __restrict__ W3, const float* __restrict__ W4)
{
    const int b = blockIdx.x;
    const int t = threadIdx.x;           // 128 threads
    if (b < 64) {
        __shared__ float w1r[2][128];
        w1r[0][t] = __ldg(W1 + (2*b)   * 128 + t);
        w1r[1][t] = __ldg(W1 + (2*b+1) * 128 + t);
        __syncthreads();
        float s0 = 0.f, s1 = 0.f;
        #pragma unroll 8
        for (int m = 0; m < 128; m++) {
            const float w2 = __ldg(W2 + m * 128 + t);
            s0 = fmaf(w1r[0][m], w2, s0);
            s1 = fmaf(w1r[1][m], w2, s1);
        }
        g_W12f[(2*b)*128 + t]   = s0;
        g_W12f[(2*b+1)*128 + t] = s1;
    } else {
        __shared__ float sw4[1024];
        #pragma unroll
        for (int i = t; i < 1024; i += 128) sw4[i] = __ldg(W4 + i);
        __syncthreads();
        const int r = (b - 64) * 16 + (t >> 3);
        const int c = t & 7;
        float s = 0.f;
        #pragma unroll 8
        for (int m = 0; m < 128; m++)
            s = fmaf(__ldg(W3 + r * 128 + m), sw4[m * 8 + c], s);
        g_W34f[r * 8 + c] = s;
    }
}

// ---------------- stage 2: frag-pack the fused fp16 image ----------------
__global__ void prep_pack(const float* __restrict__ W0,
                          const float* __restrict__ W5, const float* __restrict__ W6)
{
    const int layer = blockIdx.y;
    const int idx   = blockIdx.x * 256 + threadIdx.x;
    const int lane  = idx & 31;
    const int g     = lane >> 2;
    const int t     = lane & 3;

    if (layer <= 1) {                    // W0 (ks=0 only) / W12 (8 ks)
        const int rest = idx >> 5;
        const int ntp  = rest & 7;
        const int ks   = rest >> 3;
        if (ks > 7) return;
        if (layer == 0 && ks > 0) return;
        const int KMAX = (layer == 0) ? IN_D : 128;

        uint32_t hi[4];
        #pragma unroll
        for (int h = 0; h < 2; h++) {
            const int n  = (2*ntp + h) * 8 + g;
            const int kb = ks * 16;
            const int kr[4] = { kb + 2*t, kb + 2*t + 1, kb + 2*t + 8, kb + 2*t + 9 };
            float v[4];
            #pragma unroll
            for (int i = 0; i < 4; i++) {
                if (kr[i] >= KMAX) { v[i] = 0.f; continue; }
                v[i] = (layer == 0) ? __ldg(W0 + kr[i] * 128 + n)
                                    : g_W12f[kr[i] * 128 + n];
            }
            hi[2*h]   = packf16(v[0], v[1]);
            hi[2*h+1] = packf16(v[2], v[3]);
        }
        const size_t lbase = (layer == 0) ? 0 : 4096;
        const size_t off   = (size_t)((ks*8 + ntp) * 32 + lane) * 16;
        *(uint4*)(&g_W[lbase + off]) = make_uint4(hi[0],hi[1],hi[2],hi[3]);
        return;
    }

    if (layer == 2) {                    // W34 [128][8] tail layout
        if (idx >= 256) return;
        const int ks = idx >> 5;
        const int kb = ks * 16;
        const int kr[4] = { kb + 2*t, kb + 2*t + 1, kb + 2*t + 8, kb + 2*t + 9 };
        float v[4];
        #pragma unroll
        for (int i = 0; i < 4; i++) v[i] = g_W34f[kr[i] * 8 + g];
        uint2* dst = (uint2*)(&g_W[36864 + (size_t)(ks*32 + lane) * 8]);
        *dst = make_uint2(packf16(v[0], v[1]), packf16(v[2], v[3]));
        return;
    }
    // layer 3: W56 = W5@W6 [8][10], k pad16, n pad16
    if (idx >= 32) return;
    const int kr[4] = { 2*t, 2*t + 1, 2*t + 8, 2*t + 9 };
    uint32_t w[4];
    #pragma unroll
    for (int h = 0; h < 2; h++) {
        const int n = h * 8 + g;
        float v[4];
        #pragma unroll
        for (int i = 0; i < 4; i++) {
            float s = 0.f;
            if (kr[i] < 8 && n < IN_D) {
                #pragma unroll
                for (int m = 0; m < 8; m++)
                    s += __ldg(W5 + kr[i] * NP + m) * __ldg(W6 + m * IN_D + n);
            }
            v[i] = s;
        }
        w[2*h]   = packf16(v[0], v[1]);
        w[2*h+1] = packf16(v[2], v[3]);
    }
    *(uint4*)(&g_W[38912 + (size_t)lane * 16]) = make_uint4(w[0],w[1],w[2],w[3]);
}

// pack one nt-pair (j) of finished accs into next-layer A chunk j; zero accs
template <bool RELU>
__device__ __forceinline__ void pack_nt(float acc[2][16][4], uint32_t aH[2][8][4],
                                        uint32_t biasLA, int c, int j)
{
    #pragma unroll
    for (int h = 0; h < 2; h++) {
        const int nt = 2*j + h;
        uint32_t bh;
        LDS32U(bh, biasLA + (uint32_t)((nt*4 + c)*4));
        #pragma unroll
        for (int mt = 0; mt < 2; mt++) {
            uint32_t p0 = packf16(acc[mt][nt][0], acc[mt][nt][1]);
            uint32_t p1 = packf16(acc[mt][nt][2], acc[mt][nt][3]);
            HADD2(p0, bh); HADD2(p1, bh);
            if (RELU) { HMAX2Z(p0); HMAX2Z(p1); }
            aH[mt][j][2*h]   = p0;
            aH[mt][j][2*h+1] = p1;
            acc[mt][nt][0]=0.f; acc[mt][nt][1]=0.f;
            acc[mt][nt][2]=0.f; acc[mt][nt][3]=0.f;
        }
    }
}

// full layer + folded boundary
template <int NKS, bool RELU>
__device__ __forceinline__ void run_layer_fold(float acc[2][16][4], uint32_t aH[2][8][4],
                                               uint32_t wbase, uint32_t biasLA,
                                               int lane, int c)
{
    const uint32_t lof = (uint32_t)lane * 16u;
    #pragma unroll
    for (int ks = 0; ks < NKS - 1; ks++) {
        uint32_t w[8][4];
        #pragma unroll
        for (int ntp = 0; ntp < 8; ntp++)
            LDS128(w[ntp][0],w[ntp][1],w[ntp][2],w[ntp][3],
                   wbase + (uint32_t)((ks*8 + ntp)*32)*16u + lof);
        #pragma unroll
        for (int ntp = 0; ntp < 8; ntp++) {
            #pragma unroll
            for (int mt = 0; mt < 2; mt++) {
                MMA_F16(acc[mt][2*ntp],   aH[mt][ks][0],aH[mt][ks][1],aH[mt][ks][2],aH[mt][ks][3], w[ntp][0],w[ntp][1]);
                MMA_F16(acc[mt][2*ntp+1], aH[mt][ks][0],aH[mt][ks][1],aH[mt][ks][2],aH[mt][ks][3], w[ntp][2],w[ntp][3]);
            }
        }
    }
    {   // last ks: MMAs with pack(ntp-1) folded in
        const int ks = NKS - 1;
        uint32_t w[8][4];
        #pragma unroll
        for (int ntp = 0; ntp < 8; ntp++)
            LDS128(w[ntp][0],w[ntp][1],w[ntp][2],w[ntp][3],
                   wbase + (uint32_t)((ks*8 + ntp)*32)*16u + lof);
        #pragma unroll
        for (int ntp = 0; ntp < 8; ntp++) {
            #pragma unroll
            for (int mt = 0; mt < 2; mt++) {
                MMA_F16(acc[mt][2*ntp],   aH[mt][ks][0],aH[mt][ks][1],aH[mt][ks][2],aH[mt][ks][3], w[ntp][0],w[ntp][1]);
                MMA_F16(acc[mt][2*ntp+1], aH[mt][ks][0],aH[mt][ks][1],aH[mt][ks][2],aH[mt][ks][3], w[ntp][2],w[ntp][3]);
            }
            if (ntp > 0) pack_nt<RELU>(acc, aH, biasLA, c, ntp - 1);
        }
        pack_nt<RELU>(acc, aH, biasLA, c, 7);
    }
}

// L0 (single k-slice) with folded boundary
__device__ __forceinline__ void run_layer0_fold(float acc[2][16][4], uint32_t aH[2][8][4],
                                                uint32_t wbase, uint32_t biasLA,
                                                int lane, int c)
{
    const uint32_t lof = (uint32_t)lane * 16u;
    uint32_t a0[2][4];
    #pragma unroll
    for (int mt = 0; mt < 2; mt++)
        #pragma unroll
        for (int i = 0; i < 4; i++) a0[mt][i] = aH[mt][0][i];

    #pragma unroll
    for (int ntp = 0; ntp < 8; ntp++) {
        uint32_t w0,w1,w2,w3;
        LDS128(w0,w1,w2,w3, wbase + (uint32_t)(ntp*32)*16u + lof);
        #pragma unroll
        for (int mt = 0; mt < 2; mt++) {
            MMA_F16(acc[mt][2*ntp],   a0[mt][0],a0[mt][1],a0[mt][2],a0[mt][3], w0,w1);
            MMA_F16(acc[mt][2*ntp+1], a0[mt][0],a0[mt][1],a0[mt][2],a0[mt][3], w2,w3);
        }
        if (ntp > 0) pack_nt<true>(acc, aH, biasLA, c, ntp - 1);
    }
    pack_nt<true>(acc, aH, biasLA, c, 7);
}

__device__ __forceinline__ float frag_val(const float* srow, int col){
    if (col >= IN_D) return 0.f;
    const int off = (col == 0) ? 8 : (col == 9) ? 9 : (col - 1);
    return srow[off];
}

// ---------------- main kernel: fused net, persistent, resident weights ----------------
__global__ void __launch_bounds__(THREADS, 2)
ElementGNN_fz_kernel(const float* __restrict__ data,
                     const int*   __restrict__ elements,
                     const float* __restrict__ b0,
                     const float* __restrict__ b1, const float* __restrict__ b2,
                     const float* __restrict__ W2,
                     const float* __restrict__ b3, const float* __restrict__ b4,
                     const float* __restrict__ W4,
                     const float* __restrict__ b5, const float* __restrict__ b6,
                     const float* __restrict__ W6,
                     float* __restrict__ out, int k)
{
    extern __shared__ char smraw[];
    const uint32_t raw = smem_u32(smraw);
    const uint32_t s0  = (raw + 1023u) & ~1023u;
    char* base = smraw + (s0 - raw);

    const uint32_t wL0   = s0;                     // 4KB
    const uint32_t wW12  = s0 + 4096u;             // 32KB
    const uint32_t wW34  = s0 + 36864u;            // 2KB
    const uint32_t wW56  = s0 + 38912u;            // 512B
    float* s_in  = (float*)(base + 39424);         // [128][10] staging (5120B)
    const uint32_t sInA = s0 + 39424u;
    int* sE0 = (int*)(base + 44544);               // 512B (also b12 temp)
    int* sE1 = (int*)(base + 45056);               // 512B (also b34 temp)
    const uint32_t biasH = s0 + 45568u;            // [2][16][4] u32 (512B)
    uint32_t* biasHp = (uint32_t*)(base + 45568);
    float* sB = (float*)(base + 46080);            // b34p[4] @u32, b56f[10] @ +32
    const uint32_t sBA = s0 + 46080u;
    const uint32_t fullW = s0 + 46144u;

    const int tid  = threadIdx.x;
    const int warp = tid >> 5;
    const int lane = tid & 31;
    const int gr = lane >> 2, c = lane & 3;
    const int row = warp * 32 + lane;
    const int STRIDE = gridDim.x * TILE_M;

    if (tid == 0) { MBAR_INIT(fullW, 1); FENCE_PROXY(); }
    __syncthreads();
    if (tid == 0) { MBAR_EXPECT(fullW, W_BYTES); bulk_copy(wL0, &g_W[0], W_BYTES, fullW); }

    // ---- fused bias staging ----
    float* tmp12 = (float*)sE0;    // 128 floats
    float* tmp34 = (float*)sE1;    // 8 floats
    if (tid < 128) {               // b12 = b2 + b1 @ W2
        float s = __ldg(b2 + tid);
        #pragma unroll 8
        for (int m = 0; m < 128; m++)
            s = fmaf(__ldg(b1 + m), __ldg(W2 + m * 128 + tid), s);
        tmp12[tid] = s;
    }
    if (tid < 8) {                 // b34 = b4 + b3 @ W4
        float s = __ldg(b4 + tid);
        #pragma unroll 8
        for (int m = 0; m < 128; m++)
            s = fmaf(__ldg(b3 + m), __ldg(W4 + m * NP + tid), s);
        tmp34[tid] = s;
    }
    if (tid < 10) {                // b56 = b6 + b5 @ W6
        float s = __ldg(b6 + tid);
        #pragma unroll
        for (int i = 0; i < 8; i++) s += __ldg(b5 + i) * __ldg(W6 + i * IN_D + tid);
        sB[8 + tid] = s;
    }
    __syncthreads();
    {   // pack fp16x2 bias tables
        const int i = tid;         // 0..127 = [layer(2)][nt(16)][c(4)]
        const int layer = i >> 6, r = i & 63, nt = r >> 2, cc = r & 3;
        float v0, v1;
        if (layer == 0) { v0 = __ldg(b0 + nt*8 + 2*cc); v1 = __ldg(b0 + nt*8 + 2*cc + 1); }
        else            { v0 = tmp12[nt*8 + 2*cc];      v1 = tmp12[nt*8 + 2*cc + 1]; }
        biasHp[i] = packf16(v0, v1);
        if (tid < 4)
            ((uint32_t*)sB)[tid] = packf16(tmp34[2*tid], tmp34[2*tid + 1]);
    }
    __syncthreads();
    const float* b56f = sB + 8;

    // ---- prologue gather for tile 0 (overwrites sE0) ----
    const int tb0 = blockIdx.x * TILE_M;
    int evN;
    {
        const int pos0 = tb0 + row;
        const int ev0 = __ldg(elements + ((pos0 < k) ? pos0 : (k - 1)));
        const int e0 = ev0 / NP1;
        sE0[row] = e0;
        const int le = (e0 == 0) ? (k - 1) : (e0 - 1);
        const int ri = (e0 == k - 1) ? 0 : (e0 + 1);
        const uint32_t dst = sInA + (uint32_t)row * 40u;
        const float* so = data + (size_t)e0 * NP;
        CP_ASYNC8(dst,      so);
        CP_ASYNC8(dst + 8,  so + 2);
        CP_ASYNC8(dst + 16, so + 4);
        CP_ASYNC8(dst + 24, so + 6);
        CP_ASYNC4(dst + 32, data + (size_t)le * NP + (NP - 1));
        CP_ASYNC4(dst + 36, data + (size_t)ri * NP);
        CP_COMMIT();
        const int pos1 = tb0 + STRIDE + row;
        evN = __ldg(elements + ((pos1 < k) ? pos1 : (k - 1)));
    }
    __syncthreads();
    mbar_wait(fullW, 0);

    float acc[2][16][4];
    #pragma unroll
    for (int mt = 0; mt < 2; mt++)
        #pragma unroll
        for (int i = 0; i < 16; i++) {
            acc[mt][i][0]=0.f; acc[mt][i][1]=0.f; acc[mt][i][2]=0.f; acc[mt][i][3]=0.f;
        }

    int p = 0;
    for (int tb = tb0; tb < k; tb += STRIDE) {
        int* sE_cur = p ? sE1 : sE0;
        int* sE_nxt = p ? sE0 : sE1;

        CP_WAIT0();
        __syncwarp();

        // layer-0 A frags from staging
        uint32_t aH[2][8][4];
        #pragma unroll
        for (int mt = 0; mt < 2; mt++) {
            const float* srow0 = s_in + (size_t)(warp*32 + mt*16 + gr) * 10;
            const float* srow1 = srow0 + 80;
            const int cols[4] = { 2*c, 2*c+1, 2*c+8, 2*c+9 };
            float f0[4], f1[4];
            #pragma unroll
            for (int i = 0; i < 4; i++) {
                f0[i] = frag_val(srow0, cols[i]);
                f1[i] = frag_val(srow1, cols[i]);
            }
            aH[mt][0][0] = packf16(f0[0], f0[1]);
            aH[mt][0][1] = packf16(f1[0], f1[1]);
            aH[mt][0][2] = packf16(f0[2], f0[3]);
            aH[mt][0][3] = packf16(f1[2], f1[3]);
        }

        // issue next-tile gather
        const int nb = tb + STRIDE;
        if (nb < k) {
            const int eN = evN / NP1;
            sE_nxt[row] = eN;
            const int le = (eN == 0) ? (k - 1) : (eN - 1);
            const int ri = (eN == k - 1) ? 0 : (eN + 1);
            const uint32_t dst = sInA + (uint32_t)row * 40u;
            const float* so = data + (size_t)eN * NP;
            CP_ASYNC8(dst,      so);
            CP_ASYNC8(dst + 8,  so + 2);
            CP_ASYNC8(dst + 16, so + 4);
            CP_ASYNC8(dst + 24, so + 6);
            CP_ASYNC4(dst + 32, data + (size_t)le * NP + (NP - 1));
            CP_ASYNC4(dst + 36, data + (size_t)ri * NP);
            const int pos2 = nb + STRIDE + row;
            evN = __ldg(elements + ((pos2 < k) ? pos2 : (k - 1)));
        }
        CP_COMMIT();

        // trunk: L0 (relu) then W12 (relu), folded boundaries
        run_layer0_fold(acc, aH, wL0, biasH + 0*256u, lane, c);
        run_layer_fold<8, true>(acc, aH, wW12, biasH + 1*256u, lane, c);
        // aH = fp16(a2), acc zeroed

        // ---- hoisted residual loads ----
        float rvA[2][2], rvB[2][2];
        #pragma unroll
        for (int mt = 0; mt < 2; mt++) {
            #pragma unroll
            for (int rh = 0; rh < 2; rh++) {
                const int rowT = warp*32 + mt*16 + rh*8 + gr;
                const int pos  = tb + rowT;
                rvA[mt][rh] = 0.f; rvB[mt][rh] = 0.f;
                if (pos < k) {
                    const int eR = sE_cur[rowT];
                    const float* dp = data + (size_t)eR * NP;
                    if (c == 0) {
                        rvA[mt][rh] = __ldg(dp + 0);
                        rvB[mt][rh] = __ldg(dp + 7);
                    } else {
                        rvA[mt][rh] = __ldg(dp + 2*c - 1);
                        rvB[mt][rh] = __ldg(dp + 2*c);
                    }
                }
            }
        }

        // ---- W34: 128 -> 8 (two 4-deep chains per mt for ILP) ----
        float a4A[2][4], a4B[2][4];
        #pragma unroll
        for (int mt = 0; mt < 2; mt++)
            #pragma unroll
            for (int i = 0; i < 4; i++) { a4A[mt][i] = 0.f; a4B[mt][i] = 0.f; }
        {
            const uint32_t tb2 = wW34 + (uint32_t)lane * 8u;
            #pragma unroll
            for (int ks = 0; ks < 4; ks++) {
                uint32_t w0, w1;
                LDS64(w0, w1, tb2 + (uint32_t)ks * 256u);
                MMA_F16(a4A[0], aH[0][ks][0],aH[0][ks][1],aH[0][ks][2],aH[0][ks][3], w0, w1);
                MMA_F16(a4A[1], aH[1][ks][0],aH[1][ks][1],aH[1][ks][2],aH[1][ks][3], w0, w1);
            }
            #pragma unroll
            for (int ks = 4; ks < 8; ks++) {
                uint32_t w0, w1;
                LDS64(w0, w1, tb2 + (uint32_t)ks * 256u);
                MMA_F16(a4B[0], aH[0][ks][0],aH[0][ks][1],aH[0][ks][2],aH[0][ks][3], w0, w1);
                MMA_F16(a4B[1], aH[1][ks][0],aH[1][ks][1],aH[1][ks][2],aH[1][ks][3], w0, w1);
            }
        }
        uint32_t hA[2][2];
        {
            uint32_t b34h; LDS32U(b34h, sBA + (uint32_t)c * 4u);
            #pragma unroll
            for (int mt = 0; mt < 2; mt++) {
                uint32_t q0 = packf16(a4A[mt][0]+a4B[mt][0], a4A[mt][1]+a4B[mt][1]);
                uint32_t q1 = packf16(a4A[mt][2]+a4B[mt][2], a4A[mt][3]+a4B[mt][3]);
                HADD2(q0, b34h); HADD2(q1, b34h);
                HMAX2Z(q0); HMAX2Z(q1);
                hA[mt][0] = q0; hA[mt][1] = q1;
            }
        }
        // ---- W56: 8 -> 10 ----
        float a6[2][2][4];
        #pragma unroll
        for (int mt = 0; mt < 2; mt++)
            #pragma unroll
            for (int nt = 0; nt < 2; nt++) {
                a6[mt][nt][0]=0.f; a6[mt][nt][1]=0.f; a6[mt][nt][2]=0.f; a6[mt][nt][3]=0.f;
            }
        {
            uint32_t w0, w1, w2, w3;
            LDS128(w0, w1, w2, w3, wW56 + (uint32_t)lane * 16u);
            #pragma unroll
            for (int mt = 0; mt < 2; mt++) {
                MMA_F16(a6[mt][0], hA[mt][0], hA[mt][1], 0u, 0u, w0, w1);
                MMA_F16(a6[mt][1], hA[mt][0], hA[mt][1], 0u, 0u, w2, w3);
            }
        }

        // residual + store
        {
            const float b6c0 = b56f[2*c], b6c1 = b56f[2*c + 1];
            const float b6c8 = b56f[8];
            #pragma unroll
            for (int mt = 0; mt < 2; mt++) {
                #pragma unroll
                for (int rh = 0; rh < 2; rh++) {
                    const int rowT = warp*32 + mt*16 + rh*8 + gr;
                    const int pos  = tb + rowT;
                    if (pos < k) {
                        const float f0 = a6[mt][0][rh*2 + 0];
                        const float f1 = a6[mt][0][rh*2 + 1];
                        const float f8 = a6[mt][1][rh*2 + 0];
                        float* op = out + (size_t)pos * NP;
                        if (c == 0) {
                            op[0] = f1 + b6c1 + rvA[mt][rh];
                            op[7] = f8 + b6c8 + rvB[mt][rh];
                        } else {
                            op[2*c - 1] = f0 + b6c0 + rvA[mt][rh];
                            op[2*c]     = f1 + b6c1 + rvB[mt][rh];
                        }
                    }
                }
            }
        }
        p ^= 1;
    }
}

// ---------------- launch ----------------
extern "C" void kernel_launch(void* const* d_in, const int* in_sizes, int n_in,
                              void* d_out, int out_size)
{
    const float* data     = (const float*)d_in[0];
    const int*   elements = (const int*)  d_in[1];
    const float* W0 = (const float*)d_in[2];  const float* b0 = (const float*)d_in[3];
    const float* W1 = (const float*)d_in[4];  const float* b1 = (const float*)d_in[5];
    const float* W2 = (const float*)d_in[6];  const float* b2 = (const float*)d_in[7];
    const float* W3 = (const float*)d_in[8];  const float* b3 = (const float*)d_in[9];
    const float* W4 = (const float*)d_in[10]; const float* b4 = (const float*)d_in[11];
    const float* W5 = (const float*)d_in[12]; const float* b5 = (const float*)d_in[13];
    const float* W6 = (const float*)d_in[14]; const float* b6 = (const float*)d_in[15];
    float* out = (float*)d_out;

    const int k = in_sizes[1];

    prep_fuse<<<72, 128>>>(W1, W2, W3, W4);
    prep_pack<<<dim3(8, 4), 256>>>(W0, W5, W6);

    int tiles = (k + TILE_M - 1) / TILE_M;
    int grid  = (tiles < 296) ? tiles : 296;
    const size_t smem = 46152u + 1024u;
    cudaFuncSetAttribute(ElementGNN_fz_kernel,
                         cudaFuncAttributeMaxDynamicSharedMemorySize, (int)smem);
    ElementGNN_fz_kernel<<<grid, THREADS, smem>>>(
        data, elements, b0, b1, b2, W2, b3, b4, W4, b5, b6, W6, out, k);
}